// round 3
// baseline (speedup 1.0000x reference)
#include <cuda_runtime.h>
#include <cuda_bf16.h>
#include <math.h>

// ============================================================================
// GraphSAGE 3-layer forward, fp32.
//   L1/L2: h = relu(BN(mean_agg(x) @ Wl^T + b + x @ Wr^T))
//   L3:    o = log_softmax(mean_agg(h2) @ W3l^T + b3 + h2 @ W3r^T)
// Key transforms:
//   * mean_agg is linear -> project FIRST, aggregate projected features.
//   * BN(eval) folded into weights/bias.
//   * CSR-by-dst built per call (no float atomics in aggregation).
// ============================================================================

#define NN 100000
#define EE 1600000

// -------------------- device scratch (static, no allocation) ---------------
__device__ float g_yr[(size_t)NN * 256];     // [y | r] per layer (reused)
__device__ float g_h[(size_t)NN * 128];      // hidden activations
__device__ int   g_deg[NN];
__device__ int   g_rowptr[NN + 1];
__device__ int   g_cursor[NN];
__device__ int   g_col[EE];
__device__ int   g_part[64];
__device__ float g_Wf1[256 * 128];
__device__ float g_Wf2[256 * 128];
__device__ float g_Wf3[128 * 128];
__device__ float g_bias1[128];
__device__ float g_bias2[128];

// -------------------- weight folding ---------------------------------------
__global__ void prep_weights(
    const float* __restrict__ W1l, const float* __restrict__ W1r,
    const float* __restrict__ b1,  const float* __restrict__ g1,
    const float* __restrict__ be1, const float* __restrict__ rm1,
    const float* __restrict__ rv1,
    const float* __restrict__ W2l, const float* __restrict__ W2r,
    const float* __restrict__ b2,  const float* __restrict__ g2,
    const float* __restrict__ be2, const float* __restrict__ rm2,
    const float* __restrict__ rv2,
    const float* __restrict__ W3l, const float* __restrict__ W3r)
{
    int idx = blockIdx.x * blockDim.x + threadIdx.x;
    if (idx < 32768) {
        int j = idx >> 7, k = idx & 127;
        if (j < 128) {
            float s = g1[j] * rsqrtf(rv1[j] + 1e-5f);
            g_Wf1[idx] = s * W1l[j * 128 + k];
        } else {
            int j2 = j - 128;
            float s = g1[j2] * rsqrtf(rv1[j2] + 1e-5f);
            g_Wf1[idx] = s * W1r[j2 * 128 + k];
        }
    } else if (idx < 65536) {
        int t = idx - 32768;
        int j = t >> 7, k = t & 127;
        if (j < 128) {
            float s = g2[j] * rsqrtf(rv2[j] + 1e-5f);
            g_Wf2[t] = s * W2l[j * 128 + k];
        } else {
            int j2 = j - 128;
            float s = g2[j2] * rsqrtf(rv2[j2] + 1e-5f);
            g_Wf2[t] = s * W2r[j2 * 128 + k];
        }
    } else if (idx < 81920) {
        int t = idx - 65536;
        int j = t >> 7, k = t & 127;
        if (j < 64) g_Wf3[t] = W3l[j * 128 + k];
        else        g_Wf3[t] = W3r[(j - 64) * 128 + k];
    } else if (idx < 82048) {
        int j = idx - 81920;
        float s = g1[j] * rsqrtf(rv1[j] + 1e-5f);
        g_bias1[j] = s * (b1[j] - rm1[j]) + be1[j];
    } else if (idx < 82176) {
        int j = idx - 82048;
        float s = g2[j] * rsqrtf(rv2[j] + 1e-5f);
        g_bias2[j] = s * (b2[j] - rm2[j]) + be2[j];
    }
}

// -------------------- CSR build ---------------------------------------------
__global__ void zero_deg(int n)
{
    int i = blockIdx.x * blockDim.x + threadIdx.x;
    if (i < n) g_deg[i] = 0;
}

__global__ void count_deg(const int* __restrict__ dst, int e)
{
    int i = blockIdx.x * blockDim.x + threadIdx.x;
    if (i < e) atomicAdd(&g_deg[dst[i]], 1);
}

// 2048 elements / block, 256 threads, 8 elems / thread
__global__ void scan1(int n)
{
    __shared__ int s[256];
    int tid = threadIdx.x;
    int base = blockIdx.x * 2048;
    int vals[8];
    int run = 0;
#pragma unroll
    for (int j = 0; j < 8; j++) {
        int idx = base + tid * 8 + j;
        int v = (idx < n) ? g_deg[idx] : 0;
        vals[j] = run;
        run += v;
    }
    s[tid] = run;
    __syncthreads();
    for (int off = 1; off < 256; off <<= 1) {
        int t = (tid >= off) ? s[tid - off] : 0;
        __syncthreads();
        s[tid] += t;
        __syncthreads();
    }
    int excl = s[tid] - run;
#pragma unroll
    for (int j = 0; j < 8; j++) {
        int idx = base + tid * 8 + j;
        if (idx < n) g_rowptr[idx] = excl + vals[j];
    }
    if (tid == 255) g_part[blockIdx.x] = s[255];
}

__global__ void scan2(int nb)
{
    if (threadIdx.x == 0) {
        int run = 0;
        for (int b = 0; b < nb; b++) {
            int v = g_part[b];
            g_part[b] = run;
            run += v;
        }
    }
}

__global__ void scan3(int n, int e)
{
    int i = blockIdx.x * blockDim.x + threadIdx.x;
    if (i < n) {
        int v = g_rowptr[i] + g_part[i >> 11];
        g_rowptr[i] = v;
        g_cursor[i] = v;
    }
    if (i == 0) g_rowptr[n] = e;
}

__global__ void fill_csr(const int* __restrict__ src, const int* __restrict__ dst, int e)
{
    int i = blockIdx.x * blockDim.x + threadIdx.x;
    if (i < e) {
        int d = dst[i];
        int p = atomicAdd(&g_cursor[d], 1);
        g_col[p] = src[i];
    }
}

// -------------------- GEMM: C[M,Nout] = A[M,128] * W[Nout,128]^T ------------
// Tile: 128 rows x 64 cols, 256 threads, each thread 8x4 outputs. K = 128.
__global__ __launch_bounds__(256) void gemm_k128(
    const float* __restrict__ A, const float* __restrict__ W,
    float* __restrict__ C, int M, int Nout)
{
    __shared__ float Ws[128][64];  // [k][n]
    __shared__ float As[16][128];  // [k][m]
    const int tid = threadIdx.x;
    const int tx = tid & 15;   // col group
    const int ty = tid >> 4;   // row group
    const int m0 = blockIdx.x * 128;
    const int n0 = blockIdx.y * 64;

    // Load weight tile (whole K span) once.
#pragma unroll
    for (int it = 0; it < 8; it++) {
        int i = tid + it * 256;       // 0..2047 float4s
        int n = i & 63;
        int kq = i >> 6;              // 0..31
        float4 w = reinterpret_cast<const float4*>(W + (size_t)(n0 + n) * 128)[kq];
        Ws[kq * 4 + 0][n] = w.x; Ws[kq * 4 + 1][n] = w.y;
        Ws[kq * 4 + 2][n] = w.z; Ws[kq * 4 + 3][n] = w.w;
    }

    float acc[8][4];
#pragma unroll
    for (int r = 0; r < 8; r++)
#pragma unroll
        for (int c = 0; c < 4; c++) acc[r][c] = 0.f;

    for (int k0 = 0; k0 < 128; k0 += 16) {
        __syncthreads();
#pragma unroll
        for (int it = 0; it < 2; it++) {
            int i = tid + it * 256;   // 0..511 float4s
            int m = i & 127;
            int kq = i >> 7;          // 0..3
            int gm = m0 + m;
            float4 a = make_float4(0.f, 0.f, 0.f, 0.f);
            if (gm < M)
                a = reinterpret_cast<const float4*>(A + (size_t)gm * 128 + k0)[kq];
            As[kq * 4 + 0][m] = a.x; As[kq * 4 + 1][m] = a.y;
            As[kq * 4 + 2][m] = a.z; As[kq * 4 + 3][m] = a.w;
        }
        __syncthreads();
#pragma unroll
        for (int kk = 0; kk < 16; kk++) {
            float4 a0 = *reinterpret_cast<const float4*>(&As[kk][ty * 8]);
            float4 a1 = *reinterpret_cast<const float4*>(&As[kk][ty * 8 + 4]);
            float4 bb = *reinterpret_cast<const float4*>(&Ws[k0 + kk][tx * 4]);
            float av[8] = {a0.x, a0.y, a0.z, a0.w, a1.x, a1.y, a1.z, a1.w};
            float bv[4] = {bb.x, bb.y, bb.z, bb.w};
#pragma unroll
            for (int r = 0; r < 8; r++)
#pragma unroll
                for (int c = 0; c < 4; c++)
                    acc[r][c] += av[r] * bv[c];
        }
    }

#pragma unroll
    for (int r = 0; r < 8; r++) {
        int m = m0 + ty * 8 + r;
        if (m < M) {
            float4 o = make_float4(acc[r][0], acc[r][1], acc[r][2], acc[r][3]);
            *reinterpret_cast<float4*>(C + (size_t)m * Nout + n0 + tx * 4) = o;
        }
    }
}

// -------------------- aggregation + bias + ReLU (layers 1,2) ----------------
// One warp per node; yr row layout: [0..128)=y (aggregate), [128..256)=r (self).
__global__ void agg_relu_kernel(const float* __restrict__ yr,
                                const float* __restrict__ bias,
                                float* __restrict__ h, int n)
{
    int w = (blockIdx.x * blockDim.x + threadIdx.x) >> 5;
    int lane = threadIdx.x & 31;
    if (w >= n) return;
    int s = g_rowptr[w], e = g_rowptr[w + 1];
    float4 acc = make_float4(0.f, 0.f, 0.f, 0.f);
    for (int e0 = s; e0 < e; e0 += 32) {
        int c = 0;
        if (e0 + lane < e) c = g_col[e0 + lane];
        int cnt = min(32, e - e0);
        for (int j = 0; j < cnt; j++) {
            int cj = __shfl_sync(0xffffffffu, c, j);
            float4 v = *reinterpret_cast<const float4*>(yr + (size_t)cj * 256 + lane * 4);
            acc.x += v.x; acc.y += v.y; acc.z += v.z; acc.w += v.w;
        }
    }
    float inv = 1.f / (float)max(e - s, 1);
    float4 r = *reinterpret_cast<const float4*>(yr + (size_t)w * 256 + 128 + lane * 4);
    float4 b = *reinterpret_cast<const float4*>(bias + lane * 4);
    float4 o;
    o.x = fmaxf(fmaf(acc.x, inv, r.x + b.x), 0.f);
    o.y = fmaxf(fmaf(acc.y, inv, r.y + b.y), 0.f);
    o.z = fmaxf(fmaf(acc.z, inv, r.z + b.z), 0.f);
    o.w = fmaxf(fmaf(acc.w, inv, r.w + b.w), 0.f);
    *reinterpret_cast<float4*>(h + (size_t)w * 128 + lane * 4) = o;
}

// -------------------- layer-3 aggregation + bias + log_softmax --------------
// yr3 row layout (stride 128): [0..64)=y3, [64..128)=r3. Output 64 wide.
__global__ void agg3_lsm_kernel(const float* __restrict__ yr,
                                const float* __restrict__ b3,
                                float* __restrict__ out, int n)
{
    int w = (blockIdx.x * blockDim.x + threadIdx.x) >> 5;
    int lane = threadIdx.x & 31;
    if (w >= n) return;
    int s = g_rowptr[w], e = g_rowptr[w + 1];
    float2 acc = make_float2(0.f, 0.f);
    for (int e0 = s; e0 < e; e0 += 32) {
        int c = 0;
        if (e0 + lane < e) c = g_col[e0 + lane];
        int cnt = min(32, e - e0);
        for (int j = 0; j < cnt; j++) {
            int cj = __shfl_sync(0xffffffffu, c, j);
            float2 v = *reinterpret_cast<const float2*>(yr + (size_t)cj * 128 + lane * 2);
            acc.x += v.x; acc.y += v.y;
        }
    }
    float inv = 1.f / (float)max(e - s, 1);
    float2 r = *reinterpret_cast<const float2*>(yr + (size_t)w * 128 + 64 + lane * 2);
    float2 b = *reinterpret_cast<const float2*>(b3 + lane * 2);
    float vx = fmaf(acc.x, inv, r.x + b.x);
    float vy = fmaf(acc.y, inv, r.y + b.y);

    float m = fmaxf(vx, vy);
#pragma unroll
    for (int off = 16; off >= 1; off >>= 1)
        m = fmaxf(m, __shfl_xor_sync(0xffffffffu, m, off));
    float se = expf(vx - m) + expf(vy - m);
#pragma unroll
    for (int off = 16; off >= 1; off >>= 1)
        se += __shfl_xor_sync(0xffffffffu, se, off);
    float lse = m + logf(se);
    float2 o = make_float2(vx - lse, vy - lse);
    *reinterpret_cast<float2*>(out + (size_t)w * 64 + lane * 2) = o;
}

// -------------------- launch ------------------------------------------------
extern "C" void kernel_launch(void* const* d_in, const int* in_sizes, int n_in,
                              void* d_out, int out_size)
{
    const float* x   = (const float*)d_in[0];
    const int*   src = (const int*)d_in[1];
    const int*   dst = (const int*)d_in[2];
    const float* W1l = (const float*)d_in[3];
    const float* W1r = (const float*)d_in[4];
    const float* b1  = (const float*)d_in[5];
    const float* g1  = (const float*)d_in[6];
    const float* be1 = (const float*)d_in[7];
    const float* rm1 = (const float*)d_in[8];
    const float* rv1 = (const float*)d_in[9];
    const float* W2l = (const float*)d_in[10];
    const float* W2r = (const float*)d_in[11];
    const float* b2  = (const float*)d_in[12];
    const float* g2  = (const float*)d_in[13];
    const float* be2 = (const float*)d_in[14];
    const float* rm2 = (const float*)d_in[15];
    const float* rv2 = (const float*)d_in[16];
    const float* W3l = (const float*)d_in[17];
    const float* W3r = (const float*)d_in[18];
    const float* b3  = (const float*)d_in[19];
    float* out = (float*)d_out;

    const int n = in_sizes[0] / 128;   // 100000
    const int e = in_sizes[1];         // 1600000

    float *p_yr, *p_h, *p_Wf1, *p_Wf2, *p_Wf3, *p_b1, *p_b2;
    cudaGetSymbolAddress((void**)&p_yr,  g_yr);
    cudaGetSymbolAddress((void**)&p_h,   g_h);
    cudaGetSymbolAddress((void**)&p_Wf1, g_Wf1);
    cudaGetSymbolAddress((void**)&p_Wf2, g_Wf2);
    cudaGetSymbolAddress((void**)&p_Wf3, g_Wf3);
    cudaGetSymbolAddress((void**)&p_b1,  g_bias1);
    cudaGetSymbolAddress((void**)&p_b2,  g_bias2);

    // --- prep: fold BN into weights/bias ---
    prep_weights<<<(82176 + 255) / 256, 256>>>(
        W1l, W1r, b1, g1, be1, rm1, rv1,
        W2l, W2r, b2, g2, be2, rm2, rv2, W3l, W3r);

    // --- CSR by dst ---
    zero_deg<<<(n + 255) / 256, 256>>>(n);
    count_deg<<<(e + 255) / 256, 256>>>(dst, e);
    int nb = (n + 2047) / 2048;
    scan1<<<nb, 256>>>(n);
    scan2<<<1, 32>>>(nb);
    scan3<<<(n + 255) / 256, 256>>>(n, e);
    fill_csr<<<(e + 255) / 256, 256>>>(src, dst, e);

    const int gm = (n + 127) / 128;        // GEMM row blocks
    const int ab = (n * 32 + 255) / 256;   // agg: warp per node

    // --- layer 1 ---
    gemm_k128<<<dim3(gm, 4), 256>>>(x, p_Wf1, p_yr, n, 256);
    agg_relu_kernel<<<ab, 256>>>(p_yr, p_b1, p_h, n);
    // --- layer 2 ---
    gemm_k128<<<dim3(gm, 4), 256>>>(p_h, p_Wf2, p_yr, n, 256);
    agg_relu_kernel<<<ab, 256>>>(p_yr, p_b2, p_h, n);
    // --- layer 3 + log_softmax ---
    gemm_k128<<<dim3(gm, 2), 256>>>(p_h, p_Wf3, p_yr, n, 128);
    agg3_lsm_kernel<<<ab, 256>>>(p_yr, b3, out, n);
}

// round 4
// speedup vs baseline: 1.4677x; 1.4677x over previous
#include <cuda_runtime.h>
#include <cuda_bf16.h>
#include <math.h>
#include <stdint.h>

// ============================================================================
// GraphSAGE 3-layer forward.
//   * project-then-aggregate (mean_agg commutes with linear layers)
//   * BN(eval) folded into weights/bias
//   * CSR-by-dst built per call; warp-per-node gather (no float atomics)
//   * GEMMs on tensor cores: fp32 split into bf16 hi/lo, 3-term mma.sync
// ============================================================================

#define NN 100000
#define EE 1600000

// -------------------- device scratch (static, no allocation) ---------------
__device__ float g_yr[(size_t)NN * 256];     // [y | r] per layer (reused)
__device__ float g_h[(size_t)NN * 128];      // hidden activations
__device__ int   g_deg[NN];
__device__ int   g_rowptr[NN + 1];
__device__ int   g_cursor[NN];
__device__ int   g_col[EE];
__device__ int   g_part[64];
__device__ float g_Wf1[256 * 128];
__device__ float g_Wf2[256 * 128];
__device__ float g_Wf3[128 * 128];
__device__ float g_bias1[128];
__device__ float g_bias2[128];

// -------------------- weight folding ---------------------------------------
__global__ void prep_weights(
    const float* __restrict__ W1l, const float* __restrict__ W1r,
    const float* __restrict__ b1,  const float* __restrict__ g1,
    const float* __restrict__ be1, const float* __restrict__ rm1,
    const float* __restrict__ rv1,
    const float* __restrict__ W2l, const float* __restrict__ W2r,
    const float* __restrict__ b2,  const float* __restrict__ g2,
    const float* __restrict__ be2, const float* __restrict__ rm2,
    const float* __restrict__ rv2,
    const float* __restrict__ W3l, const float* __restrict__ W3r)
{
    int idx = blockIdx.x * blockDim.x + threadIdx.x;
    if (idx < 32768) {
        int j = idx >> 7, k = idx & 127;
        if (j < 128) {
            float s = g1[j] * rsqrtf(rv1[j] + 1e-5f);
            g_Wf1[idx] = s * W1l[j * 128 + k];
        } else {
            int j2 = j - 128;
            float s = g1[j2] * rsqrtf(rv1[j2] + 1e-5f);
            g_Wf1[idx] = s * W1r[j2 * 128 + k];
        }
    } else if (idx < 65536) {
        int t = idx - 32768;
        int j = t >> 7, k = t & 127;
        if (j < 128) {
            float s = g2[j] * rsqrtf(rv2[j] + 1e-5f);
            g_Wf2[t] = s * W2l[j * 128 + k];
        } else {
            int j2 = j - 128;
            float s = g2[j2] * rsqrtf(rv2[j2] + 1e-5f);
            g_Wf2[t] = s * W2r[j2 * 128 + k];
        }
    } else if (idx < 81920) {
        int t = idx - 65536;
        int j = t >> 7, k = t & 127;
        if (j < 64) g_Wf3[t] = W3l[j * 128 + k];
        else        g_Wf3[t] = W3r[(j - 64) * 128 + k];
    } else if (idx < 82048) {
        int j = idx - 81920;
        float s = g1[j] * rsqrtf(rv1[j] + 1e-5f);
        g_bias1[j] = s * (b1[j] - rm1[j]) + be1[j];
    } else if (idx < 82176) {
        int j = idx - 82048;
        float s = g2[j] * rsqrtf(rv2[j] + 1e-5f);
        g_bias2[j] = s * (b2[j] - rm2[j]) + be2[j];
    }
}

// -------------------- CSR build ---------------------------------------------
__global__ void zero_deg(int n)
{
    int i = blockIdx.x * blockDim.x + threadIdx.x;
    if (i < n) g_deg[i] = 0;
}

__global__ void count_deg(const int* __restrict__ dst, int e)
{
    int i = blockIdx.x * blockDim.x + threadIdx.x;
    if (i < e) atomicAdd(&g_deg[dst[i]], 1);
}

// 2048 elements / block, 256 threads, 8 elems / thread
__global__ void scan1(int n)
{
    __shared__ int s[256];
    int tid = threadIdx.x;
    int base = blockIdx.x * 2048;
    int vals[8];
    int run = 0;
#pragma unroll
    for (int j = 0; j < 8; j++) {
        int idx = base + tid * 8 + j;
        int v = (idx < n) ? g_deg[idx] : 0;
        vals[j] = run;
        run += v;
    }
    s[tid] = run;
    __syncthreads();
    for (int off = 1; off < 256; off <<= 1) {
        int t = (tid >= off) ? s[tid - off] : 0;
        __syncthreads();
        s[tid] += t;
        __syncthreads();
    }
    int excl = s[tid] - run;
#pragma unroll
    for (int j = 0; j < 8; j++) {
        int idx = base + tid * 8 + j;
        if (idx < n) g_rowptr[idx] = excl + vals[j];
    }
    if (tid == 255) g_part[blockIdx.x] = s[255];
}

__global__ void scan2(int nb)
{
    if (threadIdx.x == 0) {
        int run = 0;
        for (int b = 0; b < nb; b++) {
            int v = g_part[b];
            g_part[b] = run;
            run += v;
        }
    }
}

__global__ void scan3(int n, int e)
{
    int i = blockIdx.x * blockDim.x + threadIdx.x;
    if (i < n) {
        int v = g_rowptr[i] + g_part[i >> 11];
        g_rowptr[i] = v;
        g_cursor[i] = v;
    }
    if (i == 0) g_rowptr[n] = e;
}

__global__ void fill_csr(const int* __restrict__ src, const int* __restrict__ dst, int e)
{
    int i = blockIdx.x * blockDim.x + threadIdx.x;
    if (i < e) {
        int d = dst[i];
        int p = atomicAdd(&g_cursor[d], 1);
        g_col[p] = src[i];
    }
}

// -------------------- bf16 split helpers ------------------------------------
__device__ __forceinline__ void split_pack(float x, float y,
                                           uint32_t& hi, uint32_t& lo)
{
    // pair packed as bf16x2: low half = first element, high half = second
    __nv_bfloat16 hx = __float2bfloat16(x);
    __nv_bfloat16 hy = __float2bfloat16(y);
    __nv_bfloat16 lx = __float2bfloat16(x - __bfloat162float(hx));
    __nv_bfloat16 ly = __float2bfloat16(y - __bfloat162float(hy));
    hi = ((uint32_t)__bfloat16_as_ushort(hy) << 16) | __bfloat16_as_ushort(hx);
    lo = ((uint32_t)__bfloat16_as_ushort(ly) << 16) | __bfloat16_as_ushort(lx);
}

__device__ __forceinline__ void mma_bf16(float* c, const uint32_t* a,
                                         const uint32_t* b)
{
    asm volatile(
        "mma.sync.aligned.m16n8k16.row.col.f32.bf16.bf16.f32 "
        "{%0,%1,%2,%3}, {%4,%5,%6,%7}, {%8,%9}, {%0,%1,%2,%3};"
        : "+f"(c[0]), "+f"(c[1]), "+f"(c[2]), "+f"(c[3])
        : "r"(a[0]), "r"(a[1]), "r"(a[2]), "r"(a[3]), "r"(b[0]), "r"(b[1]));
}

// -------------------- tensor-core GEMM: C[M,Nout] = A[M,128] * W[Nout,128]^T
// CTA tile: 128 m x 64 n, K=128 in chunks of 16. 8 warps, 32x32 per warp.
// fp32 -> bf16 hi/lo split, 3-term mma (hi*hi + hi*lo + lo*hi).
// Operands stored FRAGMENT-PACKED in smem: each warp's fragment load is a
// conflict-free ld.shared at lane*16B (A, v4) / lane*8B (B, v2).
__global__ __launch_bounds__(256) void gemm_tc(
    const float* __restrict__ A, const float* __restrict__ W,
    float* __restrict__ C, int M, int Nout)
{
    // B packed: [kc(8)][nb(8)][lane(32)][reg(2)]  -> 4096 u32 each
    __shared__ uint32_t Bhi[4096], Blo[4096];
    // A packed (one 16-wide k chunk): [mb(8)][lane(32)][reg(4)] -> 1024 u32
    __shared__ uint32_t Ahi[1024], Alo[1024];

    const int tid = threadIdx.x;
    const int lane = tid & 31;
    const int w = tid >> 5;
    const int m0 = blockIdx.x * 128;
    const int n0 = blockIdx.y * 64;

    // ---- pack W tile (64 n x 128 k) once: 4096 bf16x2 pairs, 16/thread ----
#pragma unroll
    for (int it = 0; it < 16; it++) {
        int pi = tid + it * 256;        // 0..4095
        int nl = pi >> 6;               // 0..63 local n
        int p  = pi & 63;               // pair index along k (col = 2p)
        const float* wp = W + (size_t)(n0 + nl) * 128 + 2 * p;
        uint32_t hi, lo;
        split_pack(wp[0], wp[1], hi, lo);
        int kc  = p >> 3;
        int pp  = p & 7;
        int g   = nl & 7, nb = nl >> 3;
        int tig = pp & 3;
        int reg = (pp >= 4) ? 1 : 0;
        int idx = (((kc * 8 + nb) * 32) + g * 4 + tig) * 2 + reg;
        Bhi[idx] = hi; Blo[idx] = lo;
    }

    float acc[2][4][4];
#pragma unroll
    for (int i = 0; i < 2; i++)
#pragma unroll
        for (int j = 0; j < 4; j++)
#pragma unroll
            for (int k = 0; k < 4; k++) acc[i][j][k] = 0.f;

    const int mb0 = (w & 3) * 2;   // 2 m-fragments (16 rows each)
    const int nb0 = (w >> 2) * 4;  // 4 n-fragments (8 cols each)

    for (int kc = 0; kc < 8; kc++) {
        __syncthreads();   // prev compute done / B pack done
        // ---- pack A chunk (128 m x 16 k): 1024 pairs, 4/thread ----
#pragma unroll
        for (int it = 0; it < 4; it++) {
            int pi = tid + it * 256;    // 0..1023
            int m = pi >> 3;
            int p = pi & 7;             // col = 2p within chunk
            int gm = m0 + m;
            float vx = 0.f, vy = 0.f;
            if (gm < M) {
                float2 v = *reinterpret_cast<const float2*>(
                    A + (size_t)gm * 128 + kc * 16 + 2 * p);
                vx = v.x; vy = v.y;
            }
            uint32_t hi, lo;
            split_pack(vx, vy, hi, lo);
            int row = m & 15;
            int g = row & 7, rh = row >> 3;
            int tig = p & 3;
            int reg = rh + ((p >= 4) ? 2 : 0);
            int idx = ((m >> 4) * 32 + g * 4 + tig) * 4 + reg;
            Ahi[idx] = hi; Alo[idx] = lo;
        }
        __syncthreads();

        // ---- fragment loads (conflict-free) ----
        uint32_t ah[2][4], al[2][4], bh[4][2], bl[4][2];
#pragma unroll
        for (int mf = 0; mf < 2; mf++) {
            int base = ((mb0 + mf) * 32 + lane) * 4;
            *reinterpret_cast<uint4*>(ah[mf]) =
                *reinterpret_cast<const uint4*>(&Ahi[base]);
            *reinterpret_cast<uint4*>(al[mf]) =
                *reinterpret_cast<const uint4*>(&Alo[base]);
        }
#pragma unroll
        for (int nf = 0; nf < 4; nf++) {
            int base = ((kc * 8 + nb0 + nf) * 32 + lane) * 2;
            *reinterpret_cast<uint2*>(bh[nf]) =
                *reinterpret_cast<const uint2*>(&Bhi[base]);
            *reinterpret_cast<uint2*>(bl[nf]) =
                *reinterpret_cast<const uint2*>(&Blo[base]);
        }

        // ---- 3-term split mma ----
#pragma unroll
        for (int mf = 0; mf < 2; mf++)
#pragma unroll
            for (int nf = 0; nf < 4; nf++) {
                mma_bf16(acc[mf][nf], ah[mf], bh[nf]);
                mma_bf16(acc[mf][nf], ah[mf], bl[nf]);
                mma_bf16(acc[mf][nf], al[mf], bh[nf]);
            }
    }

    // ---- epilogue ----
    const int g = lane >> 2, tig = lane & 3;
#pragma unroll
    for (int mf = 0; mf < 2; mf++) {
        int mrow = m0 + (mb0 + mf) * 16 + g;
#pragma unroll
        for (int nf = 0; nf < 4; nf++) {
            int col = n0 + (nb0 + nf) * 8 + tig * 2;
            if (mrow < M)
                *reinterpret_cast<float2*>(C + (size_t)mrow * Nout + col) =
                    make_float2(acc[mf][nf][0], acc[mf][nf][1]);
            if (mrow + 8 < M)
                *reinterpret_cast<float2*>(C + (size_t)(mrow + 8) * Nout + col) =
                    make_float2(acc[mf][nf][2], acc[mf][nf][3]);
        }
    }
}

// -------------------- aggregation + bias + ReLU (layers 1,2) ----------------
__global__ void agg_relu_kernel(const float* __restrict__ yr,
                                const float* __restrict__ bias,
                                float* __restrict__ h, int n)
{
    int w = (blockIdx.x * blockDim.x + threadIdx.x) >> 5;
    int lane = threadIdx.x & 31;
    if (w >= n) return;
    int s = g_rowptr[w], e = g_rowptr[w + 1];
    float4 acc = make_float4(0.f, 0.f, 0.f, 0.f);
    for (int e0 = s; e0 < e; e0 += 32) {
        int c = 0;
        if (e0 + lane < e) c = g_col[e0 + lane];
        int cnt = min(32, e - e0);
        for (int j = 0; j < cnt; j++) {
            int cj = __shfl_sync(0xffffffffu, c, j);
            float4 v = *reinterpret_cast<const float4*>(yr + (size_t)cj * 256 + lane * 4);
            acc.x += v.x; acc.y += v.y; acc.z += v.z; acc.w += v.w;
        }
    }
    float inv = 1.f / (float)max(e - s, 1);
    float4 r = *reinterpret_cast<const float4*>(yr + (size_t)w * 256 + 128 + lane * 4);
    float4 b = *reinterpret_cast<const float4*>(bias + lane * 4);
    float4 o;
    o.x = fmaxf(fmaf(acc.x, inv, r.x + b.x), 0.f);
    o.y = fmaxf(fmaf(acc.y, inv, r.y + b.y), 0.f);
    o.z = fmaxf(fmaf(acc.z, inv, r.z + b.z), 0.f);
    o.w = fmaxf(fmaf(acc.w, inv, r.w + b.w), 0.f);
    *reinterpret_cast<float4*>(h + (size_t)w * 128 + lane * 4) = o;
}

// -------------------- layer-3 aggregation + bias + log_softmax --------------
__global__ void agg3_lsm_kernel(const float* __restrict__ yr,
                                const float* __restrict__ b3,
                                float* __restrict__ out, int n)
{
    int w = (blockIdx.x * blockDim.x + threadIdx.x) >> 5;
    int lane = threadIdx.x & 31;
    if (w >= n) return;
    int s = g_rowptr[w], e = g_rowptr[w + 1];
    float2 acc = make_float2(0.f, 0.f);
    for (int e0 = s; e0 < e; e0 += 32) {
        int c = 0;
        if (e0 + lane < e) c = g_col[e0 + lane];
        int cnt = min(32, e - e0);
        for (int j = 0; j < cnt; j++) {
            int cj = __shfl_sync(0xffffffffu, c, j);
            float2 v = *reinterpret_cast<const float2*>(yr + (size_t)cj * 128 + lane * 2);
            acc.x += v.x; acc.y += v.y;
        }
    }
    float inv = 1.f / (float)max(e - s, 1);
    float2 r = *reinterpret_cast<const float2*>(yr + (size_t)w * 128 + 64 + lane * 2);
    float2 b = *reinterpret_cast<const float2*>(b3 + lane * 2);
    float vx = fmaf(acc.x, inv, r.x + b.x);
    float vy = fmaf(acc.y, inv, r.y + b.y);

    float m = fmaxf(vx, vy);
#pragma unroll
    for (int off = 16; off >= 1; off >>= 1)
        m = fmaxf(m, __shfl_xor_sync(0xffffffffu, m, off));
    float se = expf(vx - m) + expf(vy - m);
#pragma unroll
    for (int off = 16; off >= 1; off >>= 1)
        se += __shfl_xor_sync(0xffffffffu, se, off);
    float lse = m + logf(se);
    float2 o = make_float2(vx - lse, vy - lse);
    *reinterpret_cast<float2*>(out + (size_t)w * 64 + lane * 2) = o;
}

// -------------------- launch ------------------------------------------------
extern "C" void kernel_launch(void* const* d_in, const int* in_sizes, int n_in,
                              void* d_out, int out_size)
{
    const float* x   = (const float*)d_in[0];
    const int*   src = (const int*)d_in[1];
    const int*   dst = (const int*)d_in[2];
    const float* W1l = (const float*)d_in[3];
    const float* W1r = (const float*)d_in[4];
    const float* b1  = (const float*)d_in[5];
    const float* g1  = (const float*)d_in[6];
    const float* be1 = (const float*)d_in[7];
    const float* rm1 = (const float*)d_in[8];
    const float* rv1 = (const float*)d_in[9];
    const float* W2l = (const float*)d_in[10];
    const float* W2r = (const float*)d_in[11];
    const float* b2  = (const float*)d_in[12];
    const float* g2  = (const float*)d_in[13];
    const float* be2 = (const float*)d_in[14];
    const float* rm2 = (const float*)d_in[15];
    const float* rv2 = (const float*)d_in[16];
    const float* W3l = (const float*)d_in[17];
    const float* W3r = (const float*)d_in[18];
    const float* b3  = (const float*)d_in[19];
    float* out = (float*)d_out;

    const int n = in_sizes[0] / 128;   // 100000
    const int e = in_sizes[1];         // 1600000

    float *p_yr, *p_h, *p_Wf1, *p_Wf2, *p_Wf3, *p_b1, *p_b2;
    cudaGetSymbolAddress((void**)&p_yr,  g_yr);
    cudaGetSymbolAddress((void**)&p_h,   g_h);
    cudaGetSymbolAddress((void**)&p_Wf1, g_Wf1);
    cudaGetSymbolAddress((void**)&p_Wf2, g_Wf2);
    cudaGetSymbolAddress((void**)&p_Wf3, g_Wf3);
    cudaGetSymbolAddress((void**)&p_b1,  g_bias1);
    cudaGetSymbolAddress((void**)&p_b2,  g_bias2);

    // --- prep: fold BN into weights/bias ---
    prep_weights<<<(82176 + 255) / 256, 256>>>(
        W1l, W1r, b1, g1, be1, rm1, rv1,
        W2l, W2r, b2, g2, be2, rm2, rv2, W3l, W3r);

    // --- CSR by dst ---
    zero_deg<<<(n + 255) / 256, 256>>>(n);
    count_deg<<<(e + 255) / 256, 256>>>(dst, e);
    int nb = (n + 2047) / 2048;
    scan1<<<nb, 256>>>(n);
    scan2<<<1, 32>>>(nb);
    scan3<<<(n + 255) / 256, 256>>>(n, e);
    fill_csr<<<(e + 255) / 256, 256>>>(src, dst, e);

    const int gm = (n + 127) / 128;        // GEMM row blocks
    const int ab = (n * 32 + 255) / 256;   // agg: warp per node

    // --- layer 1 ---
    gemm_tc<<<dim3(gm, 4), 256>>>(x, p_Wf1, p_yr, n, 256);
    agg_relu_kernel<<<ab, 256>>>(p_yr, p_b1, p_h, n);
    // --- layer 2 ---
    gemm_tc<<<dim3(gm, 4), 256>>>(p_h, p_Wf2, p_yr, n, 256);
    agg_relu_kernel<<<ab, 256>>>(p_yr, p_b2, p_h, n);
    // --- layer 3 + log_softmax ---
    gemm_tc<<<dim3(gm, 2), 256>>>(p_h, p_Wf3, p_yr, n, 128);
    agg3_lsm_kernel<<<ab, 256>>>(p_yr, b3, out, n);
}